// round 15
// baseline (speedup 1.0000x reference)
#include <cuda_runtime.h>
#include <math.h>
#include <stdint.h>

#define NATOMS 40001
#define NBONDS 160001
#define NNB    6
#define AFDIM  133
#define BFDIM  147
#define HD     300
#define NMOLS  1000
#define ASIZE  40
#define NSEQ   (NMOLS * ASIZE)   /* 40000 */

// ---------------- scratch (static device globals; no runtime allocation) ----------------
__device__ float g_input_atom  [NATOMS * HD];
__device__ float g_message_atom[NATOMS * HD];
__device__ float g_input_bond  [NBONDS * HD];
__device__ float g_bondA       [NBONDS * HD];   // bond-message ping
__device__ float g_bondB       [NBONDS * HD];   // bond-message pong
__device__ float g_concat      [NSEQ * 3 * HD];
__device__ float g_aggW        [NSEQ * HD];
__device__ float g_msg         [NSEQ * HD];
__device__ float g_xpf         [NSEQ * 3 * HD];
__device__ float g_xpb         [NSEQ * 3 * HD];
__device__ float g_h0          [NMOLS * HD];
__device__ float g_out         [NSEQ * 2 * HD];
__device__ float g_hid         [NSEQ * HD];

// ======================= 3xTF32 split-precision tensor-core GEMM =======================
// Round 14: loader address hoisting. Row resolution (gather idx loads, 64-bit
// row-base computation) moved OUT of the K-chunk loop into per-thread base
// pointers; per-chunk access is base+kt. Also float4 B loads in !TRANSB
// (all call sites have N % 4 == 0). Numerics bit-identical to round 13.
// Single-buffer pipeline (verified fastest), BPAD=72 conflict-free,
// asymmetric hi/lo split, float2 epilogue.

__device__ __forceinline__ void mma_tf32(float c[4], const uint32_t a[4], const uint32_t b[2]) {
    asm volatile(
        "mma.sync.aligned.m16n8k8.row.col.f32.tf32.tf32.f32 "
        "{%0,%1,%2,%3}, {%4,%5,%6,%7}, {%8,%9}, {%0,%1,%2,%3};"
        : "+f"(c[0]), "+f"(c[1]), "+f"(c[2]), "+f"(c[3])
        : "r"(a[0]), "r"(a[1]), "r"(a[2]), "r"(a[3]), "r"(b[0]), "r"(b[1]));
}

__device__ __forceinline__ float f2tf32(float v) {
    uint32_t t;
    asm("cvt.rna.tf32.f32 %0, %1;" : "=r"(t) : "f"(v));
    return __uint_as_float(t);
}

__device__ __forceinline__ void split_tf32(float v, uint32_t& hi, uint32_t& lo) {
    float h = f2tf32(v);
    hi = __float_as_uint(h);
    lo = __float_as_uint(f2tf32(v - h));
}

#define BPAD 72

template<bool TRANSB, int EPI, bool DUAL, bool GATHER>
__global__ __launch_bounds__(256, 3)
void mma_gemm(const float* __restrict__ A, const float* __restrict__ B,
              const float* __restrict__ ADD, const float* __restrict__ bias,
              float* __restrict__ C, float* __restrict__ C2,
              const int* __restrict__ idxA, const int* __restrict__ idxB,
              const float* __restrict__ GA, const float* __restrict__ GB,
              int M, int N, int K)
{
    __shared__ float As[128][20];    // [m][k] raw fp32 (conflict-free)
    __shared__ float Bh[16][BPAD];   // [k][n] tf32 hi (conflict-free @72)
    __shared__ float Bl[16][BPAD];   // [k][n] tf32 lo

    const int tid  = threadIdx.x;
    const int warp = tid >> 5, lane = tid & 31;
    const int wm   = warp & 3, wn = warp >> 2;
    const int gid  = lane >> 2, tig = lane & 3;
    const int bM   = blockIdx.y * 128, bN = blockIdx.x * 64;

    const int aRow = tid >> 2;
    const int aCol = (tid & 3) * 4;

    float aR[8], bR[4];
    float c[2][4][4] = {};

    const int nCh = (K + 15) >> 4;
    const bool kVec = ((K & 3) == 0);   // row starts 16B-aligned when K % 4 == 0

    // ---- hoisted per-thread source bases (row resolution done ONCE) ----
    const float* pA[2];    // A (or gathered GA) row base + aCol
    const float* pG[2];    // gathered GB row base + aCol (GATHER only)
    bool rowOK[2];
    #pragma unroll
    for (int r = 0; r < 2; r++) {
        int gm = bM + aRow + 64 * r;
        rowOK[r] = (gm < M);
        pA[r] = nullptr; pG[r] = nullptr;
        if (rowOK[r]) {
            if (GATHER) {
                pA[r] = GA + (size_t)__ldg(&idxA[gm]) * K + aCol;
                pG[r] = GB + (size_t)__ldg(&idxB[gm]) * K + aCol;
            } else {
                pA[r] = A + (size_t)gm * K + aCol;
            }
        }
    }
    // !TRANSB B loader geometry
    const int  bKk  = tid >> 4;              // k within chunk
    const int  bCol = bN + (tid & 15) * 4;   // first of 4 columns
    const bool bColVec = ((N & 3) == 0) && (bCol + 3 < N);
    // TRANSB B loader geometry
    const int  bTk0 = (tid & 3) * 4;
    const int  bTn  = bN + (tid >> 2);
    const float* pBt = (TRANSB && bTn < N) ? B + (size_t)bTn * K + bTk0 : nullptr;

    auto loadA = [&](int kt) {
        #pragma unroll
        for (int r = 0; r < 2; r++) {
            if (!rowOK[r]) {
                #pragma unroll
                for (int i = 0; i < 4; i++) aR[r*4+i] = 0.f;
                continue;
            }
            if (GATHER) {
                if (kVec && kt + aCol + 3 < K) {
                    float4 va = __ldg((const float4*)(pA[r] + kt));
                    float4 vb = __ldg((const float4*)(pG[r] + kt));
                    aR[r*4+0] = va.x - vb.x; aR[r*4+1] = va.y - vb.y;
                    aR[r*4+2] = va.z - vb.z; aR[r*4+3] = va.w - vb.w;
                } else {
                    #pragma unroll
                    for (int i = 0; i < 4; i++)
                        aR[r*4+i] = (kt + aCol + i < K)
                            ? __ldg(pA[r] + kt + i) - __ldg(pG[r] + kt + i) : 0.f;
                }
            } else {
                if (kVec && kt + aCol + 3 < K) {
                    float4 v = __ldg((const float4*)(pA[r] + kt));
                    aR[r*4+0] = v.x; aR[r*4+1] = v.y; aR[r*4+2] = v.z; aR[r*4+3] = v.w;
                } else {
                    #pragma unroll
                    for (int i = 0; i < 4; i++)
                        aR[r*4+i] = (kt + aCol + i < K) ? __ldg(pA[r] + kt + i) : 0.f;
                }
            }
        }
    };
    auto loadB = [&](int kt) {
        if (!TRANSB) {
            int gk = kt + bKk;
            if (bColVec && gk < K) {
                float4 v = __ldg((const float4*)&B[(size_t)gk * N + bCol]);
                bR[0] = v.x; bR[1] = v.y; bR[2] = v.z; bR[3] = v.w;
            } else {
                #pragma unroll
                for (int i = 0; i < 4; i++)
                    bR[i] = (gk < K && bCol + i < N)
                        ? __ldg(&B[(size_t)gk * N + bCol + i]) : 0.f;
            }
        } else {
            if (pBt && kVec && kt + bTk0 + 3 < K) {
                float4 v = __ldg((const float4*)(pBt + kt));
                bR[0] = v.x; bR[1] = v.y; bR[2] = v.z; bR[3] = v.w;
            } else {
                #pragma unroll
                for (int i = 0; i < 4; i++)
                    bR[i] = (pBt && kt + bTk0 + i < K) ? __ldg(pBt + kt + i) : 0.f;
            }
        }
    };

    loadA(0);
    loadB(0);

    for (int ch = 0; ch < nCh; ch++) {
        // ---- STS: A raw; B split once here ----
        #pragma unroll
        for (int r = 0; r < 2; r++)
            *(float4*)&As[aRow + 64*r][aCol] =
                make_float4(aR[r*4+0], aR[r*4+1], aR[r*4+2], aR[r*4+3]);
        if (!TRANSB) {
            int k = tid >> 4, n0 = (tid & 15) * 4;
            float4 h, l;
            h.x = f2tf32(bR[0]); l.x = f2tf32(bR[0] - h.x);
            h.y = f2tf32(bR[1]); l.y = f2tf32(bR[1] - h.y);
            h.z = f2tf32(bR[2]); l.z = f2tf32(bR[2] - h.z);
            h.w = f2tf32(bR[3]); l.w = f2tf32(bR[3] - h.w);
            *(float4*)&Bh[k][n0] = h;
            *(float4*)&Bl[k][n0] = l;
        } else {
            int n = tid >> 2, k0 = (tid & 3) * 4;
            #pragma unroll
            for (int i = 0; i < 4; i++) {
                float h = f2tf32(bR[i]);
                Bh[k0 + i][n] = h;
                Bl[k0 + i][n] = f2tf32(bR[i] - h);
            }
        }
        __syncthreads();

        if (ch + 1 < nCh) {
            loadA((ch + 1) << 4);
            loadB((ch + 1) << 4);
        }

        // ---- compute chunk: A split in regs, B pre-split in smem ----
        #pragma unroll
        for (int kk = 0; kk < 16; kk += 8) {
            uint32_t ah[2][4], al[2][4], bh_[4][2], bl_[4][2];
            #pragma unroll
            for (int mt = 0; mt < 2; mt++) {
                int m0 = wm * 32 + mt * 16 + gid;
                split_tf32(As[m0    ][kk + tig    ], ah[mt][0], al[mt][0]);
                split_tf32(As[m0 + 8][kk + tig    ], ah[mt][1], al[mt][1]);
                split_tf32(As[m0    ][kk + tig + 4], ah[mt][2], al[mt][2]);
                split_tf32(As[m0 + 8][kk + tig + 4], ah[mt][3], al[mt][3]);
            }
            #pragma unroll
            for (int nt = 0; nt < 4; nt++) {
                int n0 = wn * 32 + nt * 8 + gid;
                bh_[nt][0] = __float_as_uint(Bh[kk + tig    ][n0]);
                bh_[nt][1] = __float_as_uint(Bh[kk + tig + 4][n0]);
                bl_[nt][0] = __float_as_uint(Bl[kk + tig    ][n0]);
                bl_[nt][1] = __float_as_uint(Bl[kk + tig + 4][n0]);
            }
            #pragma unroll
            for (int mt = 0; mt < 2; mt++)
                #pragma unroll
                for (int nt = 0; nt < 4; nt++) {
                    mma_tf32(c[mt][nt], ah[mt], bl_[nt]);
                    mma_tf32(c[mt][nt], al[mt], bh_[nt]);
                    mma_tf32(c[mt][nt], ah[mt], bh_[nt]);
                }
        }
        __syncthreads();
    }

    // ---- epilogue: paired 64-bit stores (N even in all uses; col even) ----
    #pragma unroll
    for (int mt = 0; mt < 2; mt++)
        #pragma unroll
        for (int nt = 0; nt < 4; nt++)
            #pragma unroll
            for (int p = 0; p < 2; p++) {
                int row = bM + wm * 32 + mt * 16 + gid + p * 8;
                int col = bN + wn * 32 + nt * 8 + tig * 2;
                if (row < M && col < N) {
                    float2 v = make_float2(c[mt][nt][p*2], c[mt][nt][p*2 + 1]);
                    if (EPI == 2) {
                        float2 ad = *(const float2*)&ADD[(size_t)row * N + col];
                        v.x += ad.x; v.y += ad.y;
                    }
                    if (EPI == 3 || EPI == 4) { v.x += bias[col]; v.y += bias[col + 1]; }
                    if (EPI == 1 || EPI == 2 || EPI == 4) {
                        v.x = fmaxf(v.x, 0.f); v.y = fmaxf(v.y, 0.f);
                    }
                    *(float2*)&C[(size_t)row * N + col] = v;
                    if (DUAL) *(float2*)&C2[(size_t)row * N + col] = v;
                }
            }
}

// ======================= float4 gather/pointwise helpers =======================
#define HD4 (HD / 4)   /* 75 */

__device__ __forceinline__ float4 f4max(float4 a, float4 b) {
    return make_float4(fmaxf(a.x,b.x), fmaxf(a.y,b.y), fmaxf(a.z,b.z), fmaxf(a.w,b.w));
}
__device__ __forceinline__ float4 f4add(float4 a, float4 b) {
    return make_float4(a.x+b.x, a.y+b.y, a.z+b.z, a.w+b.w);
}

__global__ void agg_update_kernel(const float* __restrict__ mbond, const int* __restrict__ a2b,
                                  float* __restrict__ matom)
{
    int idx = blockIdx.x * blockDim.x + threadIdx.x;
    if (idx >= NATOMS * HD4) return;
    int a = idx / HD4, h4 = idx - a * HD4;
    float4 s  = make_float4(0.f, 0.f, 0.f, 0.f);
    float4 mx = make_float4(-INFINITY, -INFINITY, -INFINITY, -INFINITY);
    #pragma unroll
    for (int j = 0; j < NNB; j++) {
        int b = __ldg(&a2b[a * NNB + j]);
        float4 v = __ldg((const float4*)&mbond[b * HD] + h4);
        s = f4add(s, v); mx = f4max(mx, v);
    }
    float4* dst = (float4*)&matom[a * HD] + h4;
    float4 cur = *dst;
    cur.x += s.x * mx.x; cur.y += s.y * mx.y; cur.z += s.z * mx.z; cur.w += s.w * mx.w;
    *dst = cur;
}

__global__ void final_concat_kernel(const float* __restrict__ mbond, const int* __restrict__ a2b,
                                    const float* __restrict__ matom, const float* __restrict__ iatom,
                                    float* __restrict__ cc)
{
    int idx = blockIdx.x * blockDim.x + threadIdx.x;
    if (idx >= NSEQ * HD4) return;
    int row = idx / HD4, h4 = idx - row * HD4;
    int a = row + 1;
    float4 s  = make_float4(0.f, 0.f, 0.f, 0.f);
    float4 mx = make_float4(-INFINITY, -INFINITY, -INFINITY, -INFINITY);
    #pragma unroll
    for (int j = 0; j < NNB; j++) {
        int b = __ldg(&a2b[a * NNB + j]);
        float4 v = __ldg((const float4*)&mbond[b * HD] + h4);
        s = f4add(s, v); mx = f4max(mx, v);
    }
    float4 agg = make_float4(s.x*mx.x, s.y*mx.y, s.z*mx.z, s.w*mx.w);
    *((float4*)&cc[row * (3*HD)] + h4)            = agg;
    *((float4*)&cc[row * (3*HD) + HD] + h4)       = __ldg((const float4*)&matom[a * HD] + h4);
    *((float4*)&cc[row * (3*HD) + 2*HD] + h4)     = __ldg((const float4*)&iatom[a * HD] + h4);
}

__global__ void msg_kernel(const float* __restrict__ aggW, const float* __restrict__ gbias,
                           float* __restrict__ msg)
{
    int idx = blockIdx.x * blockDim.x + threadIdx.x;
    if (idx >= NSEQ * HD4) return;
    int h4 = idx % HD4;
    float4 v = __ldg((const float4*)aggW + idx);
    float4 b = __ldg((const float4*)gbias + h4);
    ((float4*)msg)[idx] = make_float4(fmaxf(v.x+b.x,0.f), fmaxf(v.y+b.y,0.f),
                                      fmaxf(v.z+b.z,0.f), fmaxf(v.w+b.w,0.f));
}

__global__ void h0_kernel(const float* __restrict__ aggW, float* __restrict__ h0)
{
    int idx = blockIdx.x * blockDim.x + threadIdx.x;
    if (idx >= NMOLS * HD4) return;
    int mol = idx / HD4, h4 = idx - mol * HD4;
    float4 mx = make_float4(-INFINITY, -INFINITY, -INFINITY, -INFINITY);
    for (int t = 0; t < ASIZE; t++)
        mx = f4max(mx, __ldg((const float4*)&aggW[(mol * ASIZE + t) * HD] + h4));
    ((float4*)h0)[idx] = mx;
}

__global__ void mean_kernel(const float* __restrict__ hid, float* __restrict__ out)
{
    int idx = blockIdx.x * blockDim.x + threadIdx.x;
    if (idx >= NMOLS * HD4) return;
    int mol = idx / HD4, h4 = idx - mol * HD4;
    float4 s = make_float4(0.f, 0.f, 0.f, 0.f);
    for (int t = 0; t < ASIZE; t++)
        s = f4add(s, __ldg((const float4*)&hid[(mol * ASIZE + t) * HD] + h4));
    ((float4*)out)[idx] = make_float4(s.x*(1.f/ASIZE), s.y*(1.f/ASIZE),
                                      s.z*(1.f/ASIZE), s.w*(1.f/ASIZE));
}

// ======================= fused bidirectional GRU (packed f32x2 FMA) =======================
#define MPB 14   /* 72 blocks x 2 dirs = 144 <= 148 SMs, single wave */

__device__ __forceinline__ float sigmoidf_(float x) { return 1.f / (1.f + expf(-x)); }

__device__ __forceinline__ void fma2(uint64_t& d, uint64_t a, uint64_t b) {
    asm("fma.rn.f32x2 %0, %1, %2, %0;" : "+l"(d) : "l"(a), "l"(b));
}

__global__ __launch_bounds__(256)
void gru_fused(const float* __restrict__ xp_f, const float* __restrict__ xp_b,
               const float* __restrict__ Whh_f, const float* __restrict__ Whh_b,  // [3H, H]
               const float* __restrict__ bhh_f, const float* __restrict__ bhh_b,
               const float* __restrict__ h0, float* __restrict__ out)
{
    extern __shared__ float sm[];
    float* h_s  = sm;               // [MPB][304]
    float* gh_s = sm + MPB * 304;   // [MPB][912]

    const int tid  = threadIdx.x;
    const int dir  = blockIdx.y;
    const int mol0 = blockIdx.x * MPB;
    const int mc   = min(MPB, NMOLS - mol0);

    const float* xp  = dir ? xp_b  : xp_f;
    const float* Whh = dir ? Whh_b : Whh_f;
    const float* bhh = dir ? bhh_b : bhh_f;

    for (int i = tid; i < MPB * 304; i += 256) h_s[i] = 0.f;
    __syncthreads();
    for (int i = tid; i < mc * HD; i += 256) {
        int m = i / HD, hh = i - m * HD;
        h_s[m * 304 + hh] = h0[(mol0 + m) * HD + hh];
    }
    __syncthreads();

    const int c3ok = (tid + 768 < 3 * HD);

    for (int s = 0; s < ASIZE; s++) {
        const int t = dir ? (ASIZE - 1 - s) : s;

        uint64_t acc[4][MPB];
        #pragma unroll
        for (int j = 0; j < 4; j++)
            #pragma unroll
            for (int m = 0; m < MPB; m++) acc[j][m] = 0ull;

        for (int k = 0; k < HD; k += 4) {
            ulonglong2 w[4];
            #pragma unroll
            for (int j = 0; j < 3; j++)
                w[j] = *(const ulonglong2*)&Whh[(tid + j * 256) * HD + k];
            w[3] = c3ok ? *(const ulonglong2*)&Whh[(tid + 768) * HD + k]
                        : make_ulonglong2(0ull, 0ull);
            #pragma unroll
            for (int m = 0; m < MPB; m++) {
                ulonglong2 hv = *(const ulonglong2*)&h_s[m * 304 + k];
                #pragma unroll
                for (int j = 0; j < 4; j++) {
                    fma2(acc[j][m], w[j].x, hv.x);
                    fma2(acc[j][m], w[j].y, hv.y);
                }
            }
        }
        #pragma unroll
        for (int j = 0; j < 4; j++) {
            int cc = tid + j * 256;
            if (cc < 3 * HD) {
                float bb = bhh[cc];
                #pragma unroll
                for (int m = 0; m < MPB; m++) {
                    float2 p = *reinterpret_cast<float2*>(&acc[j][m]);
                    gh_s[m * 912 + cc] = p.x + p.y + bb;
                }
            }
        }
        __syncthreads();

        for (int i = tid; i < mc * HD; i += 256) {
            int m = i / HD, hh = i - m * HD;
            int row = (mol0 + m) * ASIZE + t;
            float ir = xp[row * (3*HD) + hh];
            float iz = xp[row * (3*HD) + HD + hh];
            float in = xp[row * (3*HD) + 2*HD + hh];
            float hr = gh_s[m * 912 + hh];
            float hz = gh_s[m * 912 + HD + hh];
            float hn = gh_s[m * 912 + 2*HD + hh];
            float r = sigmoidf_(ir + hr);
            float z = sigmoidf_(iz + hz);
            float n = tanhf(in + r * hn);
            float hp = h_s[m * 304 + hh];
            float hnew = (1.f - z) * n + z * hp;
            h_s[m * 304 + hh] = hnew;
            out[row * (2*HD) + dir * HD + hh] = hnew;
        }
        __syncthreads();
    }
}

// ======================= host orchestration =======================
static inline dim3 mma_grid(int M, int N) { return dim3((N + 63) / 64, (M + 127) / 128); }
static inline int  blocks_for(int n)      { return (n + 255) / 256; }

extern "C" void kernel_launch(void* const* d_in, const int* in_sizes, int n_in,
                              void* d_out, int out_size)
{
    const float* f_atoms  = (const float*)d_in[0];
    const float* f_bonds  = (const float*)d_in[1];
    const float* Wi_atom  = (const float*)d_in[2];
    const float* Wi_bond  = (const float*)d_in[3];
    const float* Wh0      = (const float*)d_in[4];
    const float* Wh1      = (const float*)d_in[5];
    const float* W_lr     = (const float*)d_in[6];
    const float* W_o      = (const float*)d_in[7];
    const float* b_o      = (const float*)d_in[8];
    const float* gru_bias = (const float*)d_in[9];
    const float* gWih_f   = (const float*)d_in[10];
    const float* gWhh_f   = (const float*)d_in[11];
    const float* gbih_f   = (const float*)d_in[12];
    const float* gbhh_f   = (const float*)d_in[13];
    const float* gWih_b   = (const float*)d_in[14];
    const float* gWhh_b   = (const float*)d_in[15];
    const float* gbih_b   = (const float*)d_in[16];
    const float* gbhh_b   = (const float*)d_in[17];
    const int*   a2b      = (const int*)d_in[18];
    const int*   b2a      = (const int*)d_in[19];
    const int*   b2revb   = (const int*)d_in[20];
    float* out = (float*)d_out;

    float *inA, *mA, *inB, *mB0, *mB1, *cc, *aggW, *msg, *xpf, *xpb, *h0, *gout, *hid;
    cudaGetSymbolAddress((void**)&inA,  g_input_atom);
    cudaGetSymbolAddress((void**)&mA,   g_message_atom);
    cudaGetSymbolAddress((void**)&inB,  g_input_bond);
    cudaGetSymbolAddress((void**)&mB0,  g_bondA);
    cudaGetSymbolAddress((void**)&mB1,  g_bondB);
    cudaGetSymbolAddress((void**)&cc,   g_concat);
    cudaGetSymbolAddress((void**)&aggW, g_aggW);
    cudaGetSymbolAddress((void**)&msg,  g_msg);
    cudaGetSymbolAddress((void**)&xpf,  g_xpf);
    cudaGetSymbolAddress((void**)&xpb,  g_xpb);
    cudaGetSymbolAddress((void**)&h0,   g_h0);
    cudaGetSymbolAddress((void**)&gout, g_out);
    cudaGetSymbolAddress((void**)&hid,  g_hid);

    const int gru_smem = (MPB * 304 + MPB * 912) * (int)sizeof(float);
    cudaFuncSetAttribute(gru_fused, cudaFuncAttributeMaxDynamicSharedMemorySize, gru_smem);

    // 1. input_atom = relu(f_atoms @ Wi_atom); dual-store into message_atom
    mma_gemm<false, 1, true, false><<<mma_grid(NATOMS, HD), 256>>>(
        f_atoms, Wi_atom, nullptr, nullptr, inA, mA, nullptr, nullptr, nullptr, nullptr,
        NATOMS, HD, AFDIM);

    // 2. input_bond = relu(f_bonds @ Wi_bond); dual-store into bond-message ping (mB0)
    mma_gemm<false, 1, true, false><<<mma_grid(NBONDS, HD), 256>>>(
        f_bonds, Wi_bond, nullptr, nullptr, inB, mB0, nullptr, nullptr, nullptr, nullptr,
        NBONDS, HD, BFDIM);

    // 3. two message-passing steps; mb gather fused into GEMM A-loader (ping-pong).
    agg_update_kernel<<<blocks_for(NATOMS * HD4), 256>>>(mB0, a2b, mA);
    mma_gemm<false, 2, false, true><<<mma_grid(NBONDS, HD), 256>>>(
        nullptr, Wh0, inB, nullptr, mB1, nullptr, b2a, b2revb, mA, mB0,
        NBONDS, HD, HD);
    agg_update_kernel<<<blocks_for(NATOMS * HD4), 256>>>(mB1, a2b, mA);
    mma_gemm<false, 2, false, true><<<mma_grid(NBONDS, HD), 256>>>(
        nullptr, Wh1, inB, nullptr, mB0, nullptr, b2a, b2revb, mA, mB1,
        NBONDS, HD, HD);

    // 4. final aggregation + concat + W_lr  (reads mB0; atom rows 1..NSEQ)
    final_concat_kernel<<<blocks_for(NSEQ * HD4), 256>>>(mB0, a2b, mA, inA, cc);
    mma_gemm<false, 0, false, false><<<mma_grid(NSEQ, HD), 256>>>(
        cc, W_lr, nullptr, nullptr, aggW, nullptr, nullptr, nullptr, nullptr, nullptr,
        NSEQ, HD, 3 * HD);

    // 5. BatchGRU prep
    msg_kernel<<<blocks_for(NSEQ * HD4), 256>>>(aggW, gru_bias, msg);
    h0_kernel<<<blocks_for(NMOLS * HD4), 256>>>(aggW, h0);

    // input projections: xp = msg @ Wih^T + bih
    mma_gemm<true, 3, false, false><<<mma_grid(NSEQ, 3 * HD), 256>>>(
        msg, gWih_f, nullptr, gbih_f, xpf, nullptr, nullptr, nullptr, nullptr, nullptr,
        NSEQ, 3 * HD, HD);
    mma_gemm<true, 3, false, false><<<mma_grid(NSEQ, 3 * HD), 256>>>(
        msg, gWih_b, nullptr, gbih_b, xpb, nullptr, nullptr, nullptr, nullptr, nullptr,
        NSEQ, 3 * HD, HD);

    // 6+7. both GRU directions, all 40 steps, one kernel
    {
        dim3 grid((NMOLS + MPB - 1) / MPB, 2);
        gru_fused<<<grid, 256, gru_smem>>>(xpf, xpb, gWhh_f, gWhh_b, gbhh_f, gbhh_b, h0, gout);
    }

    // 8. atom_hiddens = relu(out @ W_o + b_o); mol_vecs = per-mol mean
    mma_gemm<false, 4, false, false><<<mma_grid(NSEQ, HD), 256>>>(
        gout, W_o, nullptr, b_o, hid, nullptr, nullptr, nullptr, nullptr, nullptr,
        NSEQ, HD, 2 * HD);
    mean_kernel<<<blocks_for(NMOLS * HD4), 256>>>(hid, out);
}